// round 3
// baseline (speedup 1.0000x reference)
#include <cuda_runtime.h>
#include <cuda_bf16.h>
#include <math.h>
#include <stdint.h>

#define BB   32
#define LL   1024
#define DIN  2048
#define HH   1024
#define NLB  21
#define EE   768
#define MM   (BB*LL)
#define LN_EPS 1e-5f

__device__ float g_h[(size_t)MM * HH];
__device__ float g_labelh[NLB * HH];
__device__ float g_nll[BB];

union U2 { unsigned long long u; float2 f; };
__device__ __forceinline__ void fma2(unsigned long long& d, unsigned long long a, unsigned long long b) {
    asm("fma.rn.f32x2 %0, %1, %2, %0;" : "+l"(d) : "l"(a), "l"(b));
}
__device__ __forceinline__ unsigned long long dup2(float x) {
    unsigned long long r; unsigned int xi = __float_as_uint(x);
    asm("mov.b64 %0, {%1, %1};" : "=l"(r) : "r"(xi));
    return r;
}

// ---------------- K0: label_h = label_table @ W_lab ----------------
__global__ void k0_labelh(const float* __restrict__ lt, const float* __restrict__ wl) {
    const int n = blockIdx.y;
    const int h = blockIdx.x * 128 + threadIdx.x;
    float acc = 0.f;
    const float* ltr = lt + n * EE;
    #pragma unroll 4
    for (int e = 0; e < EE; e++) acc = fmaf(ltr[e], wl[(size_t)e * HH + h], acc);
    g_labelh[n * HH + h] = acc;
}

// ---------------- K1: g_h = seq_feats @ W_tok (fp32 FFMA2) ----------------
#define BKc 16
__global__ __launch_bounds__(256, 2)
void k1_sgemm(const float* __restrict__ A, const float* __restrict__ Bm) {
    __shared__ __align__(16) float As[2][BKc][132];
    __shared__ __align__(16) float Bs[2][BKc][128];
    const int t = threadIdx.x;
    const int cRow = blockIdx.y * 128, cCol = blockIdx.x * 128;
    const int tx = t & 15, ty = t >> 4;
    const int arow0 = t >> 2, akq = (t & 3) * 4;
    const int brow0 = t >> 5, bcq = (t & 31) * 4;
    const float* Aptr = A + (size_t)cRow * DIN;
    const float* Bptr = Bm + cCol;

    float4 a0, a1, b0, b1;
    a0 = *(const float4*)&Aptr[(size_t)arow0 * DIN + akq];
    a1 = *(const float4*)&Aptr[(size_t)(arow0 + 64) * DIN + akq];
    b0 = *(const float4*)&Bptr[(size_t)brow0 * HH + bcq];
    b1 = *(const float4*)&Bptr[(size_t)(brow0 + 8) * HH + bcq];
    As[0][akq+0][arow0] = a0.x; As[0][akq+1][arow0] = a0.y;
    As[0][akq+2][arow0] = a0.z; As[0][akq+3][arow0] = a0.w;
    As[0][akq+0][arow0+64] = a1.x; As[0][akq+1][arow0+64] = a1.y;
    As[0][akq+2][arow0+64] = a1.z; As[0][akq+3][arow0+64] = a1.w;
    *(float4*)&Bs[0][brow0][bcq] = b0;
    *(float4*)&Bs[0][brow0+8][bcq] = b1;
    __syncthreads();

    U2 acc[8][4];
    #pragma unroll
    for (int i = 0; i < 8; i++)
        #pragma unroll
        for (int j = 0; j < 4; j++) acc[i][j].u = 0ull;

    const int NK = DIN / BKc;
    int buf = 0;
    for (int kt = 0; kt < NK; kt++) {
        if (kt + 1 < NK) {
            const float* Ap = Aptr + (size_t)(kt + 1) * BKc;
            const float* Bp = Bptr + (size_t)(kt + 1) * BKc * HH;
            a0 = *(const float4*)&Ap[(size_t)arow0 * DIN + akq];
            a1 = *(const float4*)&Ap[(size_t)(arow0 + 64) * DIN + akq];
            b0 = *(const float4*)&Bp[(size_t)brow0 * HH + bcq];
            b1 = *(const float4*)&Bp[(size_t)(brow0 + 8) * HH + bcq];
        }
        #pragma unroll
        for (int k = 0; k < BKc; k++) {
            float4 ra0 = *(const float4*)&As[buf][k][ty*8];
            float4 ra1 = *(const float4*)&As[buf][k][ty*8 + 4];
            ulonglong2 rb0 = *(const ulonglong2*)&Bs[buf][k][tx*8];
            ulonglong2 rb1 = *(const ulonglong2*)&Bs[buf][k][tx*8 + 4];
            unsigned long long rb[4] = {rb0.x, rb0.y, rb1.x, rb1.y};
            float ra[8] = {ra0.x, ra0.y, ra0.z, ra0.w, ra1.x, ra1.y, ra1.z, ra1.w};
            #pragma unroll
            for (int i = 0; i < 8; i++) {
                unsigned long long ad = dup2(ra[i]);
                #pragma unroll
                for (int j = 0; j < 4; j++) fma2(acc[i][j].u, ad, rb[j]);
            }
        }
        if (kt + 1 < NK) {
            int nb = buf ^ 1;
            As[nb][akq+0][arow0] = a0.x; As[nb][akq+1][arow0] = a0.y;
            As[nb][akq+2][arow0] = a0.z; As[nb][akq+3][arow0] = a0.w;
            As[nb][akq+0][arow0+64] = a1.x; As[nb][akq+1][arow0+64] = a1.y;
            As[nb][akq+2][arow0+64] = a1.z; As[nb][akq+3][arow0+64] = a1.w;
            *(float4*)&Bs[nb][brow0][bcq] = b0;
            *(float4*)&Bs[nb][brow0+8][bcq] = b1;
            __syncthreads();
            buf = nb;
        }
    }
    float* Cp = g_h + (size_t)(cRow + ty*8) * HH + cCol + tx*8;
    #pragma unroll
    for (int i = 0; i < 8; i++) {
        float4 v0, v1;
        v0.x = acc[i][0].f.x; v0.y = acc[i][0].f.y; v0.z = acc[i][1].f.x; v0.w = acc[i][1].f.y;
        v1.x = acc[i][2].f.x; v1.y = acc[i][2].f.y; v1.z = acc[i][3].f.x; v1.w = acc[i][3].f.y;
        *(float4*)&Cp[(size_t)i * HH] = v0;
        *(float4*)&Cp[(size_t)i * HH + 4] = v1;
    }
}

// ---------------- K2: LN + exact GELU + logits = token_h @ label_h^T * T ----------------
#define RPB 16
__global__ __launch_bounds__(256)
void k2_ln_gelu_logits(const float* __restrict__ gamma, const float* __restrict__ beta,
                       const float* __restrict__ temp_p, float* __restrict__ logits) {
    extern __shared__ float smem[];
    float* slh = smem;                 // NLB*HH
    float* sth = smem + NLB * HH;      // HH
    float* red = sth + HH;             // 16
    const int t = threadIdx.x, lane = t & 31, wid = t >> 5;

    for (int i = t; i < NLB * HH; i += 256) slh[i] = g_labelh[i];
    const float tempv = *temp_p;
    const float4 g4 = *(const float4*)&gamma[t * 4];
    const float4 b4 = *(const float4*)&beta[t * 4];
    __syncthreads();

    const int row0 = blockIdx.x * RPB;
    for (int r = 0; r < RPB; r++) {
        const int row = row0 + r;
        const float4 xv = *(const float4*)&g_h[(size_t)row * HH + t * 4];
        float s = xv.x + xv.y + xv.z + xv.w;
        float q = xv.x*xv.x + xv.y*xv.y + xv.z*xv.z + xv.w*xv.w;
        #pragma unroll
        for (int o = 16; o > 0; o >>= 1) {
            s += __shfl_xor_sync(0xffffffffu, s, o);
            q += __shfl_xor_sync(0xffffffffu, q, o);
        }
        if (lane == 0) { red[wid] = s; red[8 + wid] = q; }
        __syncthreads();
        float S = 0.f, Q = 0.f;
        #pragma unroll
        for (int w = 0; w < 8; w++) { S += red[w]; Q += red[8 + w]; }
        const float mean = S * (1.f / HH);
        const float rstd = rsqrtf(Q * (1.f / HH) - mean * mean + LN_EPS);
        float xs[4] = {xv.x, xv.y, xv.z, xv.w};
        float gs[4] = {g4.x, g4.y, g4.z, g4.w};
        float bs[4] = {b4.x, b4.y, b4.z, b4.w};
        #pragma unroll
        for (int c = 0; c < 4; c++) {
            float y = (xs[c] - mean) * rstd * gs[c] + bs[c];
            sth[t * 4 + c] = 0.5f * y * (1.f + erff(y * 0.70710678118654752f));
        }
        __syncthreads();
        #pragma unroll
        for (int li = 0; li < 3; li++) {
            const int l = wid + li * 8;
            if (l < NLB) {
                float acc = 0.f;
                #pragma unroll 8
                for (int k = lane; k < HH; k += 32)
                    acc = fmaf(sth[k], slh[l * HH + k], acc);
                #pragma unroll
                for (int o = 16; o > 0; o >>= 1) acc += __shfl_xor_sync(0xffffffffu, acc, o);
                if (lane == 0) logits[(size_t)row * NLB + l] = acc * tempv;
            }
        }
        __syncthreads();
    }
}

// ---------------- K3: CRF forward (exp domain, per-step renorm) + gold score ----------------
__global__ void k3_crf(const float* __restrict__ logits, const int* __restrict__ labels,
                       const float* __restrict__ start_t, const float* __restrict__ end_t,
                       const float* __restrict__ trans) {
    __shared__ float sexpT[NLB][32];
    const int b = blockIdx.x;
    const int j = threadIdx.x;  // 32 threads
    // build exp(trans), zero-padded columns
    for (int i = 0; i < NLB; i++)
        sexpT[i][j] = (j < NLB) ? expf(trans[i * NLB + j]) : 0.f;
    __syncwarp();

    const float* lg = logits + (size_t)b * LL * NLB;
    const int* lab = labels + (size_t)b * LL;

    // init
    float a0 = (j < NLB) ? (start_t[j] + lg[j]) : -INFINITY;
    float m = a0;
    #pragma unroll
    for (int o = 16; o > 0; o >>= 1) m = fmaxf(m, __shfl_xor_sync(0xffffffffu, m, o));
    float f = expf(a0 - m);      // 0 for j>=NLB
    float logc = m;

    for (int t = 1; t < LL; t++) {
        const float e = (j < NLB) ? lg[t * NLB + j] : 0.f;
        float g = 0.f;
        #pragma unroll
        for (int i = 0; i < NLB; i++)
            g = fmaf(__shfl_sync(0xffffffffu, f, i), sexpT[i][j], g);
        float v = g * expf(e);   // 0 for j>=NLB (g==0)
        float mv = v;
        #pragma unroll
        for (int o = 16; o > 0; o >>= 1) mv = fmaxf(mv, __shfl_xor_sync(0xffffffffu, mv, o));
        f = v / mv;
        logc += logf(mv);
    }
    float sfin = (j < NLB) ? f * expf(end_t[j]) : 0.f;
    #pragma unroll
    for (int o = 16; o > 0; o >>= 1) sfin += __shfl_xor_sync(0xffffffffu, sfin, o);
    const float logZ = logc + logf(sfin);

    // gold-path score (strided over lanes)
    float sc = 0.f;
    for (int t = j; t < LL; t += 32) {
        const int lt_ = lab[t];
        sc += lg[t * NLB + lt_];
        if (t >= 1) sc += trans[lab[t - 1] * NLB + lt_];
    }
    #pragma unroll
    for (int o = 16; o > 0; o >>= 1) sc += __shfl_xor_sync(0xffffffffu, sc, o);
    if (j == 0) {
        sc += start_t[lab[0]] + end_t[lab[LL - 1]];
        g_nll[b] = logZ - sc;
    }
}

// ---------------- K4: loss = mean(nll) ----------------
__global__ void k4_loss(float* __restrict__ out_loss) {
    float v = g_nll[threadIdx.x];
    #pragma unroll
    for (int o = 16; o > 0; o >>= 1) v += __shfl_xor_sync(0xffffffffu, v, o);
    if (threadIdx.x == 0) *out_loss = v * (1.f / BB);
}

extern "C" void kernel_launch(void* const* d_in, const int* in_sizes, int n_in,
                              void* d_out, int out_size) {
    const float* seq    = (const float*)d_in[0];
    const int*   labels = (const int*)  d_in[1];
    const float* Wtok   = (const float*)d_in[3];
    const float* gamma  = (const float*)d_in[4];
    const float* beta   = (const float*)d_in[5];
    const float* ltab   = (const float*)d_in[6];
    const float* Wlab   = (const float*)d_in[7];
    const float* temp   = (const float*)d_in[8];
    const float* startt = (const float*)d_in[9];
    const float* endt   = (const float*)d_in[10];
    const float* trans  = (const float*)d_in[11];
    float* out = (float*)d_out;

    k0_labelh<<<dim3(HH / 128, NLB), 128>>>(ltab, Wlab);
    k1_sgemm<<<dim3(HH / 128, MM / 128), 256>>>(seq, Wtok);

    const int smem2 = (NLB * HH + HH + 16) * (int)sizeof(float);
    cudaFuncSetAttribute(k2_ln_gelu_logits, cudaFuncAttributeMaxDynamicSharedMemorySize, smem2);
    k2_ln_gelu_logits<<<MM / RPB, 256, smem2>>>(gamma, beta, temp, out);

    k3_crf<<<BB, 32>>>(out, labels, startt, endt, trans);
    k4_loss<<<1, 32>>>(out + (out_size - 1));
}

// round 5
// speedup vs baseline: 1.7524x; 1.7524x over previous
#include <cuda_runtime.h>
#include <cuda_bf16.h>
#include <math.h>
#include <stdint.h>

#define BB   32
#define LL   1024
#define DIN  2048
#define HH   1024
#define NLB  21
#define EE   768
#define MM   (BB*LL)
#define LN_EPS 1e-5f

// ---------------- device scratch ----------------
__device__ __align__(16) float g_h[(size_t)MM * HH];
__device__ __align__(16) __nv_bfloat16 g_ahi[(size_t)MM * DIN];
__device__ __align__(16) __nv_bfloat16 g_alo[(size_t)MM * DIN];
__device__ __align__(16) __nv_bfloat16 g_bhi[(size_t)HH * DIN];   // [n][k]
__device__ __align__(16) __nv_bfloat16 g_blo[(size_t)HH * DIN];
__device__ float g_labelh[NLB * HH];
__device__ float g_rowmax[MM];
__device__ float g_nll[BB];

// ---------------- helpers ----------------
__device__ __forceinline__ uint32_t smem_u32(const void* p) {
    uint32_t a;
    asm("{ .reg .u64 t; cvta.to.shared.u64 t, %1; cvt.u32.u64 %0, t; }" : "=r"(a) : "l"(p));
    return a;
}
#define CP16(ds, sp) asm volatile("cp.async.cg.shared.global [%0], [%1], 16;" \
    :: "r"(ds), "l"(__cvta_generic_to_global(sp)) : "memory")
#define CP_COMMIT() asm volatile("cp.async.commit_group;" ::: "memory")
#define LDSM_X4(r0, r1, r2, r3, a) asm volatile( \
    "ldmatrix.sync.aligned.m8n8.x4.shared.b16 {%0,%1,%2,%3}, [%4];" \
    : "=r"(r0), "=r"(r1), "=r"(r2), "=r"(r3) : "r"(a))
#define MMA4(d, a0, a1, a2, a3, b0, b1) asm volatile( \
    "mma.sync.aligned.m16n8k16.row.col.f32.bf16.bf16.f32 " \
    "{%0,%1,%2,%3}, {%4,%5,%6,%7}, {%8,%9}, {%0,%1,%2,%3};" \
    : "+f"((d)[0]), "+f"((d)[1]), "+f"((d)[2]), "+f"((d)[3]) \
    : "r"(a0), "r"(a1), "r"(a2), "r"(a3), "r"(b0), "r"(b1))

// ---------------- split kernels ----------------
__global__ void ksplitA(const float* __restrict__ X) {
    size_t i = ((size_t)blockIdx.x * blockDim.x + threadIdx.x) * 4;
    float4 v = *(const float4*)(X + i);
    __nv_bfloat16 h0 = __float2bfloat16(v.x), h1 = __float2bfloat16(v.y);
    __nv_bfloat16 h2 = __float2bfloat16(v.z), h3 = __float2bfloat16(v.w);
    __nv_bfloat16 l0 = __float2bfloat16(v.x - __bfloat162float(h0));
    __nv_bfloat16 l1 = __float2bfloat16(v.y - __bfloat162float(h1));
    __nv_bfloat16 l2 = __float2bfloat16(v.z - __bfloat162float(h2));
    __nv_bfloat16 l3 = __float2bfloat16(v.w - __bfloat162float(h3));
    *(__nv_bfloat162*)(g_ahi + i)     = __nv_bfloat162(h0, h1);
    *(__nv_bfloat162*)(g_ahi + i + 2) = __nv_bfloat162(h2, h3);
    *(__nv_bfloat162*)(g_alo + i)     = __nv_bfloat162(l0, l1);
    *(__nv_bfloat162*)(g_alo + i + 2) = __nv_bfloat162(l2, l3);
}

__global__ void ksplitB(const float* __restrict__ W) {
    __shared__ float tile[32][33];
    const int kb = blockIdx.x * 32, nb = blockIdx.y * 32;
    const int tx = threadIdx.x, ty = threadIdx.y;  // 32 x 8
    #pragma unroll
    for (int i = 0; i < 32; i += 8)
        tile[ty + i][tx] = W[(size_t)(kb + ty + i) * HH + nb + tx];
    __syncthreads();
    #pragma unroll
    for (int i = 0; i < 32; i += 8) {
        float v = tile[tx][ty + i];   // W[kb+tx][nb+ty+i]
        __nv_bfloat16 hi = __float2bfloat16(v);
        __nv_bfloat16 lo = __float2bfloat16(v - __bfloat162float(hi));
        size_t o = (size_t)(nb + ty + i) * DIN + kb + tx;
        g_bhi[o] = hi; g_blo[o] = lo;
    }
}

// ---------------- K0: label_h ----------------
__global__ void k0_labelh(const float* __restrict__ lt, const float* __restrict__ wl) {
    const int n = blockIdx.y;
    const int h = blockIdx.x * 128 + threadIdx.x;
    float acc = 0.f;
    const float* ltr = lt + n * EE;
    #pragma unroll 4
    for (int e = 0; e < EE; e++) acc = fmaf(ltr[e], wl[(size_t)e * HH + h], acc);
    g_labelh[n * HH + h] = acc;
}

// ---------------- K1: bf16-split GEMM via mma.sync ----------------
#define KC2 32
#define NCH2 (DIN / KC2)     // 64
#define TPITCH 80            // smem row pitch bytes (5*16B -> conflict-free ldmatrix)
#define TILEB (128 * TPITCH) // 10240 per matrix tile
#define STAGEB (4 * TILEB)   // 40960 per stage

__device__ __forceinline__ void prefetch_chunk(uint32_t sbuf, int cRow, int cCol,
                                               int k0, int tid) {
    #pragma unroll
    for (int q = 0; q < 2; q++) {
        const int id = q * 256 + tid;
        const int r = id >> 2, c4 = id & 3;
        const uint32_t dof = sbuf + (uint32_t)(r * TPITCH + c4 * 16);
        const size_t goA = (size_t)(cRow + r) * DIN + k0 + c4 * 8;
        const size_t goB = (size_t)(cCol + r) * DIN + k0 + c4 * 8;
        CP16(dof,             g_ahi + goA);
        CP16(dof + TILEB,     g_alo + goA);
        CP16(dof + 2 * TILEB, g_bhi + goB);
        CP16(dof + 3 * TILEB, g_blo + goB);
    }
}

__global__ __launch_bounds__(256, 1) void k1_mma() {
    extern __shared__ char sm[];
    const int tid = threadIdx.x, lane = tid & 31, wid = tid >> 5;
    const int cCol = blockIdx.x * 128, cRow = blockIdx.y * 128;
    const int wm = wid >> 1, wn = wid & 1;  // warp tile 32M x 64N
    const uint32_t sb = smem_u32(sm);

    float acc[2][8][4];
    #pragma unroll
    for (int i = 0; i < 2; i++)
        #pragma unroll
        for (int j = 0; j < 8; j++)
            #pragma unroll
            for (int k = 0; k < 4; k++) acc[i][j][k] = 0.f;

    prefetch_chunk(sb, cRow, cCol, 0, tid);
    CP_COMMIT();

    // per-thread ldmatrix address components
    const int aRow = wm * 32 + (lane & 15);            // + mt*16
    const uint32_t aKb = (uint32_t)((lane >> 4) * 16); // + ks*32
    const int bRow = wn * 64 + ((lane >> 4) & 1) * 8 + (lane & 7); // + p*16
    const uint32_t bKb = (uint32_t)(((lane >> 3) & 1) * 16);

    for (int c = 0; c < NCH2; c++) {
        if (c + 1 < NCH2) {
            prefetch_chunk(sb + (uint32_t)(((c + 1) & 1) * STAGEB), cRow, cCol,
                           (c + 1) * KC2, tid);
            CP_COMMIT();
            asm volatile("cp.async.wait_group 1;" ::: "memory");
        } else {
            asm volatile("cp.async.wait_group 0;" ::: "memory");
        }
        __syncthreads();
        const uint32_t st = sb + (uint32_t)((c & 1) * STAGEB);

        #pragma unroll
        for (int ks = 0; ks < 2; ks++) {
            uint32_t ah[2][4], al[2][4];
            #pragma unroll
            for (int mt = 0; mt < 2; mt++) {
                const uint32_t ao = st + (uint32_t)((aRow + mt * 16) * TPITCH) + aKb + (uint32_t)(ks * 32);
                LDSM_X4(ah[mt][0], ah[mt][1], ah[mt][2], ah[mt][3], ao);
                LDSM_X4(al[mt][0], al[mt][1], al[mt][2], al[mt][3], ao + TILEB);
            }
            #pragma unroll
            for (int p = 0; p < 4; p++) {
                const uint32_t bo = st + 2 * TILEB +
                    (uint32_t)((bRow + p * 16) * TPITCH) + bKb + (uint32_t)(ks * 32);
                uint32_t bh0, bh1, bh2, bh3, bl0, bl1, bl2, bl3;
                LDSM_X4(bh0, bh1, bh2, bh3, bo);
                LDSM_X4(bl0, bl1, bl2, bl3, bo + TILEB);
                #pragma unroll
                for (int mt = 0; mt < 2; mt++) {
                    MMA4(acc[mt][2*p],   ah[mt][0], ah[mt][1], ah[mt][2], ah[mt][3], bh0, bh1);
                    MMA4(acc[mt][2*p],   ah[mt][0], ah[mt][1], ah[mt][2], ah[mt][3], bl0, bl1);
                    MMA4(acc[mt][2*p],   al[mt][0], al[mt][1], al[mt][2], al[mt][3], bh0, bh1);
                    MMA4(acc[mt][2*p+1], ah[mt][0], ah[mt][1], ah[mt][2], ah[mt][3], bh2, bh3);
                    MMA4(acc[mt][2*p+1], ah[mt][0], ah[mt][1], ah[mt][2], ah[mt][3], bl2, bl3);
                    MMA4(acc[mt][2*p+1], al[mt][0], al[mt][1], al[mt][2], al[mt][3], bh2, bh3);
                }
            }
        }
        __syncthreads();
    }

    #pragma unroll
    for (int mt = 0; mt < 2; mt++)
        #pragma unroll
        for (int nt = 0; nt < 8; nt++) {
            const int row = cRow + wm * 32 + mt * 16 + (lane >> 2);
            const int col = cCol + wn * 64 + nt * 8 + (lane & 3) * 2;
            float2 v0 = make_float2(acc[mt][nt][0], acc[mt][nt][1]);
            float2 v1 = make_float2(acc[mt][nt][2], acc[mt][nt][3]);
            *(float2*)&g_h[(size_t)row * HH + col] = v0;
            *(float2*)&g_h[(size_t)(row + 8) * HH + col] = v1;
        }
}

// ---------------- K2: LN + exact GELU + logits ----------------
#define RPB 16
__global__ __launch_bounds__(256)
void k2_ln_gelu_logits(const float* __restrict__ gamma, const float* __restrict__ beta,
                       const float* __restrict__ temp_p, float* __restrict__ logits) {
    extern __shared__ float smem[];
    float* slh = smem;
    float* sth = smem + NLB * HH;
    float* red = sth + HH;
    const int t = threadIdx.x, lane = t & 31, wid = t >> 5;

    for (int i = t; i < NLB * HH; i += 256) slh[i] = g_labelh[i];
    const float tempv = *temp_p;
    const float4 g4 = *(const float4*)&gamma[t * 4];
    const float4 b4 = *(const float4*)&beta[t * 4];
    __syncthreads();

    const int row0 = blockIdx.x * RPB;
    for (int r = 0; r < RPB; r++) {
        const int row = row0 + r;
        const float4 xv = *(const float4*)&g_h[(size_t)row * HH + t * 4];
        float s = xv.x + xv.y + xv.z + xv.w;
        float q = xv.x*xv.x + xv.y*xv.y + xv.z*xv.z + xv.w*xv.w;
        #pragma unroll
        for (int o = 16; o > 0; o >>= 1) {
            s += __shfl_xor_sync(0xffffffffu, s, o);
            q += __shfl_xor_sync(0xffffffffu, q, o);
        }
        if (lane == 0) { red[wid] = s; red[8 + wid] = q; }
        __syncthreads();
        float S = 0.f, Q = 0.f;
        #pragma unroll
        for (int w = 0; w < 8; w++) { S += red[w]; Q += red[8 + w]; }
        const float mean = S * (1.f / HH);
        const float rstd = rsqrtf(Q * (1.f / HH) - mean * mean + LN_EPS);
        float xs[4] = {xv.x, xv.y, xv.z, xv.w};
        float gs[4] = {g4.x, g4.y, g4.z, g4.w};
        float bs[4] = {b4.x, b4.y, b4.z, b4.w};
        #pragma unroll
        for (int c = 0; c < 4; c++) {
            float y = (xs[c] - mean) * rstd * gs[c] + bs[c];
            sth[t * 4 + c] = 0.5f * y * (1.f + erff(y * 0.70710678118654752f));
        }
        __syncthreads();
        #pragma unroll
        for (int li = 0; li < 3; li++) {
            const int l = wid + li * 8;
            if (l < NLB) {
                float acc = 0.f;
                #pragma unroll 8
                for (int k = lane; k < HH; k += 32)
                    acc = fmaf(sth[k], slh[l * HH + k], acc);
                #pragma unroll
                for (int o = 16; o > 0; o >>= 1) acc += __shfl_xor_sync(0xffffffffu, acc, o);
                if (lane == 0) logits[(size_t)row * NLB + l] = acc * tempv;
            }
        }
        __syncthreads();
    }
}

// ---------------- K2b: per-row max of logits ----------------
__global__ void k2b_rowmax(const float* __restrict__ logits) {
    __shared__ float sl[256 * NLB];
    const int r0 = blockIdx.x * 256;
    for (int i = threadIdx.x; i < 256 * NLB; i += 256)
        sl[i] = logits[(size_t)r0 * NLB + i];
    __syncthreads();
    float m = sl[threadIdx.x * NLB];
    #pragma unroll
    for (int l = 1; l < NLB; l++) m = fmaxf(m, sl[threadIdx.x * NLB + l]);
    g_rowmax[r0 + threadIdx.x] = m;
}

// ---------------- K3: CRF forward (exp domain, renorm /8) ----------------
__global__ void k3_crf(const float* __restrict__ logits, const int* __restrict__ labels,
                       const float* __restrict__ start_t, const float* __restrict__ end_t,
                       const float* __restrict__ trans) {
    const int b = blockIdx.x;
    const int j = threadIdx.x;  // 32 lanes
    float eT[NLB];
    #pragma unroll
    for (int i = 0; i < NLB; i++) eT[i] = (j < NLB) ? expf(trans[i * NLB + j]) : 0.f;

    const float* lg = logits + (size_t)b * LL * NLB;
    const float* rm = g_rowmax + (size_t)b * LL;
    const int* lab = labels + (size_t)b * LL;

    float a0 = (j < NLB) ? (start_t[j] + lg[j]) : -INFINITY;
    float m = a0;
    #pragma unroll
    for (int o = 16; o > 0; o >>= 1) m = fmaxf(m, __shfl_xor_sync(0xffffffffu, m, o));
    float f = expf(a0 - m);
    float logc = m;

    float e_cur = (j < NLB) ? lg[NLB + j] : -1e30f;
    float m_cur = rm[1];
    for (int t = 1; t < LL; t++) {
        float e_next = -1e30f, m_next = 0.f;
        if (t + 1 < LL) {
            if (j < NLB) e_next = lg[(size_t)(t + 1) * NLB + j];
            m_next = rm[t + 1];
        }
        float g0 = 0.f, g1 = 0.f, g2 = 0.f;
        #pragma unroll
        for (int i = 0; i < NLB; i += 3) {
            g0 = fmaf(__shfl_sync(0xffffffffu, f, i),     eT[i],     g0);
            g1 = fmaf(__shfl_sync(0xffffffffu, f, i + 1), eT[i + 1], g1);
            g2 = fmaf(__shfl_sync(0xffffffffu, f, i + 2), eT[i + 2], g2);
        }
        float fn = ((g0 + g1) + g2) * __expf(e_cur - m_cur);
        logc += m_cur;
        if ((t & 7) == 7) {
            float mx = fn;
            #pragma unroll
            for (int o = 16; o > 0; o >>= 1) mx = fmaxf(mx, __shfl_xor_sync(0xffffffffu, mx, o));
            fn = fn / mx;
            logc += logf(mx);
        }
        f = fn; e_cur = e_next; m_cur = m_next;
    }
    float sf = (j < NLB) ? f * expf(end_t[j]) : 0.f;
    #pragma unroll
    for (int o = 16; o > 0; o >>= 1) sf += __shfl_xor_sync(0xffffffffu, sf, o);
    const float logZ = logc + logf(sf);

    float sc = 0.f;
    for (int t = j; t < LL; t += 32) {
        const int lt_ = lab[t];
        sc += lg[t * NLB + lt_];
        if (t >= 1) sc += trans[lab[t - 1] * NLB + lt_];
    }
    #pragma unroll
    for (int o = 16; o > 0; o >>= 1) sc += __shfl_xor_sync(0xffffffffu, sc, o);
    if (j == 0) {
        sc += start_t[lab[0]] + end_t[lab[LL - 1]];
        g_nll[b] = logZ - sc;
    }
}

// ---------------- K4: loss ----------------
__global__ void k4_loss(float* __restrict__ out_loss) {
    float v = g_nll[threadIdx.x];
    #pragma unroll
    for (int o = 16; o > 0; o >>= 1) v += __shfl_xor_sync(0xffffffffu, v, o);
    if (threadIdx.x == 0) *out_loss = v * (1.f / BB);
}

extern "C" void kernel_launch(void* const* d_in, const int* in_sizes, int n_in,
                              void* d_out, int out_size) {
    const float* seq    = (const float*)d_in[0];
    const int*   labels = (const int*)  d_in[1];
    const float* Wtok   = (const float*)d_in[3];
    const float* gamma  = (const float*)d_in[4];
    const float* beta   = (const float*)d_in[5];
    const float* ltab   = (const float*)d_in[6];
    const float* Wlab   = (const float*)d_in[7];
    const float* temp   = (const float*)d_in[8];
    const float* startt = (const float*)d_in[9];
    const float* endt   = (const float*)d_in[10];
    const float* trans  = (const float*)d_in[11];
    float* out = (float*)d_out;

    ksplitA<<<(int)(((size_t)MM * DIN / 4) / 256), 256>>>(seq);
    ksplitB<<<dim3(DIN / 32, HH / 32), dim3(32, 8)>>>(Wtok);
    k0_labelh<<<dim3(HH / 128, NLB), 128>>>(ltab, Wlab);

    const int smem1 = 2 * STAGEB;
    cudaFuncSetAttribute(k1_mma, cudaFuncAttributeMaxDynamicSharedMemorySize, smem1);
    k1_mma<<<dim3(HH / 128, MM / 128), 256, smem1>>>();

    const int smem2 = (NLB * HH + HH + 16) * (int)sizeof(float);
    cudaFuncSetAttribute(k2_ln_gelu_logits, cudaFuncAttributeMaxDynamicSharedMemorySize, smem2);
    k2_ln_gelu_logits<<<MM / RPB, 256, smem2>>>(gamma, beta, temp, out);

    k2b_rowmax<<<MM / 256, 256>>>(out);
    k3_crf<<<BB, 32>>>(out, labels, startt, endt, trans);
    k4_loss<<<1, 32>>>(out + (out_size - 1));
}

// round 6
// speedup vs baseline: 1.9030x; 1.0860x over previous
#include <cuda_runtime.h>
#include <cuda_bf16.h>
#include <math.h>
#include <stdint.h>

#define BB   32
#define LL   1024
#define DIN  2048
#define HH   1024
#define NLB  21
#define EE   768
#define MM   (BB*LL)
#define LN_EPS 1e-5f

// ---------------- device scratch ----------------
__device__ __align__(16) float g_h[(size_t)MM * HH];
__device__ __align__(16) __nv_bfloat16 g_ahi[(size_t)MM * DIN];
__device__ __align__(16) __nv_bfloat16 g_alo[(size_t)MM * DIN];
__device__ __align__(16) __nv_bfloat16 g_bhi[(size_t)HH * DIN];   // [n][k]
__device__ __align__(16) __nv_bfloat16 g_blo[(size_t)HH * DIN];
__device__ float g_labelh[NLB * HH];
__device__ float g_rowmax[MM];
__device__ float g_nll[BB];

// ---------------- helpers ----------------
__device__ __forceinline__ uint32_t smem_u32(const void* p) {
    uint32_t a;
    asm("{ .reg .u64 t; cvta.to.shared.u64 t, %1; cvt.u32.u64 %0, t; }" : "=r"(a) : "l"(p));
    return a;
}
#define CP16(ds, sp) asm volatile("cp.async.cg.shared.global [%0], [%1], 16;" \
    :: "r"(ds), "l"(__cvta_generic_to_global(sp)) : "memory")
#define CP_COMMIT() asm volatile("cp.async.commit_group;" ::: "memory")
#define LDSM_X4(r0, r1, r2, r3, a) asm volatile( \
    "ldmatrix.sync.aligned.m8n8.x4.shared.b16 {%0,%1,%2,%3}, [%4];" \
    : "=r"(r0), "=r"(r1), "=r"(r2), "=r"(r3) : "r"(a))
#define MMA4(d, a0, a1, a2, a3, b0, b1) asm volatile( \
    "mma.sync.aligned.m16n8k16.row.col.f32.bf16.bf16.f32 " \
    "{%0,%1,%2,%3}, {%4,%5,%6,%7}, {%8,%9}, {%0,%1,%2,%3};" \
    : "+f"((d)[0]), "+f"((d)[1]), "+f"((d)[2]), "+f"((d)[3]) \
    : "r"(a0), "r"(a1), "r"(a2), "r"(a3), "r"(b0), "r"(b1))

// ---------------- split kernels ----------------
__global__ void ksplitA(const float* __restrict__ X) {
    size_t i = ((size_t)blockIdx.x * blockDim.x + threadIdx.x) * 4;
    float4 v = *(const float4*)(X + i);
    __nv_bfloat16 h0 = __float2bfloat16(v.x), h1 = __float2bfloat16(v.y);
    __nv_bfloat16 h2 = __float2bfloat16(v.z), h3 = __float2bfloat16(v.w);
    __nv_bfloat16 l0 = __float2bfloat16(v.x - __bfloat162float(h0));
    __nv_bfloat16 l1 = __float2bfloat16(v.y - __bfloat162float(h1));
    __nv_bfloat16 l2 = __float2bfloat16(v.z - __bfloat162float(h2));
    __nv_bfloat16 l3 = __float2bfloat16(v.w - __bfloat162float(h3));
    *(__nv_bfloat162*)(g_ahi + i)     = __nv_bfloat162(h0, h1);
    *(__nv_bfloat162*)(g_ahi + i + 2) = __nv_bfloat162(h2, h3);
    *(__nv_bfloat162*)(g_alo + i)     = __nv_bfloat162(l0, l1);
    *(__nv_bfloat162*)(g_alo + i + 2) = __nv_bfloat162(l2, l3);
}

__global__ void ksplitB(const float* __restrict__ W) {
    __shared__ float tile[32][33];
    const int kb = blockIdx.x * 32, nb = blockIdx.y * 32;
    const int tx = threadIdx.x, ty = threadIdx.y;  // 32 x 8
    #pragma unroll
    for (int i = 0; i < 32; i += 8)
        tile[ty + i][tx] = W[(size_t)(kb + ty + i) * HH + nb + tx];
    __syncthreads();
    #pragma unroll
    for (int i = 0; i < 32; i += 8) {
        float v = tile[tx][ty + i];   // W[kb+tx][nb+ty+i]
        __nv_bfloat16 hi = __float2bfloat16(v);
        __nv_bfloat16 lo = __float2bfloat16(v - __bfloat162float(hi));
        size_t o = (size_t)(nb + ty + i) * DIN + kb + tx;
        g_bhi[o] = hi; g_blo[o] = lo;
    }
}

// ---------------- K0: label_h ----------------
__global__ void k0_labelh(const float* __restrict__ lt, const float* __restrict__ wl) {
    const int n = blockIdx.y;
    const int h = blockIdx.x * 128 + threadIdx.x;
    float acc = 0.f;
    const float* ltr = lt + n * EE;
    #pragma unroll 4
    for (int e = 0; e < EE; e++) acc = fmaf(ltr[e], wl[(size_t)e * HH + h], acc);
    g_labelh[n * HH + h] = acc;
}

// ---------------- K1: bf16-split GEMM via mma.sync, 128x256 tile, 512 thr ----------------
#define KC2 32
#define NCH2 (DIN / KC2)       // 64
#define TPITCH 80              // smem row pitch bytes
#define TILEA (128 * TPITCH)   // 10240
#define TILEB2 (256 * TPITCH)  // 20480
#define STAGEB (2 * TILEA + 2 * TILEB2)  // 61440

__device__ __forceinline__ void prefetch_chunk(uint32_t sbuf, int cRow, int cCol,
                                               int k0, int tid) {
    #pragma unroll
    for (int q = 0; q < 6; q++) {
        const int id = q * 512 + tid;
        const int c4 = id & 3;
        if (id < 1024) {             // A tiles: 128 rows x 4 xfers, hi then lo
            const int r = (id >> 2) & 127;
            const bool hi = id < 512;
            const __nv_bfloat16* src = hi ? g_ahi : g_alo;
            const uint32_t dof = sbuf + (hi ? 0u : (uint32_t)TILEA)
                               + (uint32_t)(r * TPITCH + c4 * 16);
            CP16(dof, src + (size_t)(cRow + r) * DIN + k0 + c4 * 8);
        } else {                     // B tiles: 256 rows x 4 xfers, hi then lo
            const int r = (id >> 2) & 255;
            const bool hi = id < 2048;
            const __nv_bfloat16* src = hi ? g_bhi : g_blo;
            const uint32_t dof = sbuf + 2u * TILEA + (hi ? 0u : (uint32_t)TILEB2)
                               + (uint32_t)(r * TPITCH + c4 * 16);
            CP16(dof, src + (size_t)(cCol + r) * DIN + k0 + c4 * 8);
        }
    }
}

__global__ __launch_bounds__(512, 1) void k1_mma() {
    extern __shared__ char sm[];
    const int tid = threadIdx.x, lane = tid & 31, wid = tid >> 5;
    const int cCol = blockIdx.x * 256, cRow = blockIdx.y * 128;
    const int wm = wid >> 2, wn = wid & 3;  // warp tile 32M x 64N
    const uint32_t sb = smem_u32(sm);

    float acc[2][8][4];
    #pragma unroll
    for (int i = 0; i < 2; i++)
        #pragma unroll
        for (int j = 0; j < 8; j++)
            #pragma unroll
            for (int k = 0; k < 4; k++) acc[i][j][k] = 0.f;

    prefetch_chunk(sb, cRow, cCol, 0, tid);
    CP_COMMIT();

    const int aRow = wm * 32 + (lane & 15);            // + mt*16
    const uint32_t aKb = (uint32_t)((lane >> 4) * 16); // + ks*32
    const int bRow = wn * 64 + ((lane >> 4) & 1) * 8 + (lane & 7); // + p*16
    const uint32_t bKb = (uint32_t)(((lane >> 3) & 1) * 16);

    for (int c = 0; c < NCH2; c++) {
        if (c + 1 < NCH2) {
            prefetch_chunk(sb + (uint32_t)(((c + 1) & 1) * STAGEB), cRow, cCol,
                           (c + 1) * KC2, tid);
            CP_COMMIT();
            asm volatile("cp.async.wait_group 1;" ::: "memory");
        } else {
            asm volatile("cp.async.wait_group 0;" ::: "memory");
        }
        __syncthreads();
        const uint32_t st = sb + (uint32_t)((c & 1) * STAGEB);

        #pragma unroll
        for (int ks = 0; ks < 2; ks++) {
            uint32_t ah[2][4], al[2][4];
            #pragma unroll
            for (int mt = 0; mt < 2; mt++) {
                const uint32_t ao = st + (uint32_t)((aRow + mt * 16) * TPITCH) + aKb + (uint32_t)(ks * 32);
                LDSM_X4(ah[mt][0], ah[mt][1], ah[mt][2], ah[mt][3], ao);
                LDSM_X4(al[mt][0], al[mt][1], al[mt][2], al[mt][3], ao + TILEA);
            }
            #pragma unroll
            for (int p = 0; p < 4; p++) {
                const uint32_t bo = st + 2u * TILEA +
                    (uint32_t)((bRow + p * 16) * TPITCH) + bKb + (uint32_t)(ks * 32);
                uint32_t bh0, bh1, bh2, bh3, bl0, bl1, bl2, bl3;
                LDSM_X4(bh0, bh1, bh2, bh3, bo);
                LDSM_X4(bl0, bl1, bl2, bl3, bo + TILEB2);
                #pragma unroll
                for (int mt = 0; mt < 2; mt++) {
                    MMA4(acc[mt][2*p],   ah[mt][0], ah[mt][1], ah[mt][2], ah[mt][3], bh0, bh1);
                    MMA4(acc[mt][2*p],   ah[mt][0], ah[mt][1], ah[mt][2], ah[mt][3], bl0, bl1);
                    MMA4(acc[mt][2*p],   al[mt][0], al[mt][1], al[mt][2], al[mt][3], bh0, bh1);
                    MMA4(acc[mt][2*p+1], ah[mt][0], ah[mt][1], ah[mt][2], ah[mt][3], bh2, bh3);
                    MMA4(acc[mt][2*p+1], ah[mt][0], ah[mt][1], ah[mt][2], ah[mt][3], bl2, bl3);
                    MMA4(acc[mt][2*p+1], al[mt][0], al[mt][1], al[mt][2], al[mt][3], bh2, bh3);
                }
            }
        }
        __syncthreads();
    }

    #pragma unroll
    for (int mt = 0; mt < 2; mt++)
        #pragma unroll
        for (int nt = 0; nt < 8; nt++) {
            const int row = cRow + wm * 32 + mt * 16 + (lane >> 2);
            const int col = cCol + wn * 64 + nt * 8 + (lane & 3) * 2;
            float2 v0 = make_float2(acc[mt][nt][0], acc[mt][nt][1]);
            float2 v1 = make_float2(acc[mt][nt][2], acc[mt][nt][3]);
            *(float2*)&g_h[(size_t)row * HH + col] = v0;
            *(float2*)&g_h[(size_t)(row + 8) * HH + col] = v1;
        }
}

// ---------------- K2: LN + exact GELU + logits ----------------
#define RPB 16
__global__ __launch_bounds__(256)
void k2_ln_gelu_logits(const float* __restrict__ gamma, const float* __restrict__ beta,
                       const float* __restrict__ temp_p, float* __restrict__ logits) {
    extern __shared__ float smem[];
    float* slh = smem;
    float* sth = smem + NLB * HH;
    float* red = sth + HH;
    const int t = threadIdx.x, lane = t & 31, wid = t >> 5;

    for (int i = t; i < NLB * HH; i += 256) slh[i] = g_labelh[i];
    const float tempv = *temp_p;
    const float4 g4 = *(const float4*)&gamma[t * 4];
    const float4 b4 = *(const float4*)&beta[t * 4];
    __syncthreads();

    const int row0 = blockIdx.x * RPB;
    for (int r = 0; r < RPB; r++) {
        const int row = row0 + r;
        const float4 xv = *(const float4*)&g_h[(size_t)row * HH + t * 4];
        float s = xv.x + xv.y + xv.z + xv.w;
        float q = xv.x*xv.x + xv.y*xv.y + xv.z*xv.z + xv.w*xv.w;
        #pragma unroll
        for (int o = 16; o > 0; o >>= 1) {
            s += __shfl_xor_sync(0xffffffffu, s, o);
            q += __shfl_xor_sync(0xffffffffu, q, o);
        }
        if (lane == 0) { red[wid] = s; red[8 + wid] = q; }
        __syncthreads();
        float S = 0.f, Q = 0.f;
        #pragma unroll
        for (int w = 0; w < 8; w++) { S += red[w]; Q += red[8 + w]; }
        const float mean = S * (1.f / HH);
        const float rstd = rsqrtf(Q * (1.f / HH) - mean * mean + LN_EPS);
        float xs[4] = {xv.x, xv.y, xv.z, xv.w};
        float gs[4] = {g4.x, g4.y, g4.z, g4.w};
        float bs[4] = {b4.x, b4.y, b4.z, b4.w};
        #pragma unroll
        for (int c = 0; c < 4; c++) {
            float y = (xs[c] - mean) * rstd * gs[c] + bs[c];
            sth[t * 4 + c] = 0.5f * y * (1.f + erff(y * 0.70710678118654752f));
        }
        __syncthreads();
        #pragma unroll
        for (int li = 0; li < 3; li++) {
            const int l = wid + li * 8;
            if (l < NLB) {
                float acc = 0.f;
                #pragma unroll 8
                for (int k = lane; k < HH; k += 32)
                    acc = fmaf(sth[k], slh[l * HH + k], acc);
                #pragma unroll
                for (int o = 16; o > 0; o >>= 1) acc += __shfl_xor_sync(0xffffffffu, acc, o);
                if (lane == 0) logits[(size_t)row * NLB + l] = acc * tempv;
            }
        }
        __syncthreads();
    }
}

// ---------------- K2b: per-row max of logits ----------------
__global__ void k2b_rowmax(const float* __restrict__ logits) {
    __shared__ float sl[256 * NLB];
    const int r0 = blockIdx.x * 256;
    for (int i = threadIdx.x; i < 256 * NLB; i += 256)
        sl[i] = logits[(size_t)r0 * NLB + i];
    __syncthreads();
    float m = sl[threadIdx.x * NLB];
    #pragma unroll
    for (int l = 1; l < NLB; l++) m = fmaxf(m, sl[threadIdx.x * NLB + l]);
    g_rowmax[r0 + threadIdx.x] = m;
}

// ---------------- K3: CRF forward (exp domain, renorm /8) ----------------
__global__ void k3_crf(const float* __restrict__ logits, const int* __restrict__ labels,
                       const float* __restrict__ start_t, const float* __restrict__ end_t,
                       const float* __restrict__ trans) {
    const int b = blockIdx.x;
    const int j = threadIdx.x;  // 32 lanes
    float eT[NLB];
    #pragma unroll
    for (int i = 0; i < NLB; i++) eT[i] = (j < NLB) ? expf(trans[i * NLB + j]) : 0.f;

    const float* lg = logits + (size_t)b * LL * NLB;
    const float* rm = g_rowmax + (size_t)b * LL;
    const int* lab = labels + (size_t)b * LL;

    float a0 = (j < NLB) ? (start_t[j] + lg[j]) : -INFINITY;
    float m = a0;
    #pragma unroll
    for (int o = 16; o > 0; o >>= 1) m = fmaxf(m, __shfl_xor_sync(0xffffffffu, m, o));
    float f = expf(a0 - m);
    float logc = m;

    float e_cur = (j < NLB) ? lg[NLB + j] : -1e30f;
    float m_cur = rm[1];
    for (int t = 1; t < LL; t++) {
        float e_next = -1e30f, m_next = 0.f;
        if (t + 1 < LL) {
            if (j < NLB) e_next = lg[(size_t)(t + 1) * NLB + j];
            m_next = rm[t + 1];
        }
        float g0 = 0.f, g1 = 0.f, g2 = 0.f;
        #pragma unroll
        for (int i = 0; i < NLB; i += 3) {
            g0 = fmaf(__shfl_sync(0xffffffffu, f, i),     eT[i],     g0);
            g1 = fmaf(__shfl_sync(0xffffffffu, f, i + 1), eT[i + 1], g1);
            g2 = fmaf(__shfl_sync(0xffffffffu, f, i + 2), eT[i + 2], g2);
        }
        float fn = ((g0 + g1) + g2) * __expf(e_cur - m_cur);
        logc += m_cur;
        if ((t & 7) == 7) {
            float mx = fn;
            #pragma unroll
            for (int o = 16; o > 0; o >>= 1) mx = fmaxf(mx, __shfl_xor_sync(0xffffffffu, mx, o));
            fn = fn / mx;
            logc += logf(mx);
        }
        f = fn; e_cur = e_next; m_cur = m_next;
    }
    float sf = (j < NLB) ? f * expf(end_t[j]) : 0.f;
    #pragma unroll
    for (int o = 16; o > 0; o >>= 1) sf += __shfl_xor_sync(0xffffffffu, sf, o);
    const float logZ = logc + logf(sf);

    float sc = 0.f;
    for (int t = j; t < LL; t += 32) {
        const int lt_ = lab[t];
        sc += lg[t * NLB + lt_];
        if (t >= 1) sc += trans[lab[t - 1] * NLB + lt_];
    }
    #pragma unroll
    for (int o = 16; o > 0; o >>= 1) sc += __shfl_xor_sync(0xffffffffu, sc, o);
    if (j == 0) {
        sc += start_t[lab[0]] + end_t[lab[LL - 1]];
        g_nll[b] = logZ - sc;
    }
}

// ---------------- K4: loss ----------------
__global__ void k4_loss(float* __restrict__ out_loss) {
    float v = g_nll[threadIdx.x];
    #pragma unroll
    for (int o = 16; o > 0; o >>= 1) v += __shfl_xor_sync(0xffffffffu, v, o);
    if (threadIdx.x == 0) *out_loss = v * (1.f / BB);
}

extern "C" void kernel_launch(void* const* d_in, const int* in_sizes, int n_in,
                              void* d_out, int out_size) {
    const float* seq    = (const float*)d_in[0];
    const int*   labels = (const int*)  d_in[1];
    const float* Wtok   = (const float*)d_in[3];
    const float* gamma  = (const float*)d_in[4];
    const float* beta   = (const float*)d_in[5];
    const float* ltab   = (const float*)d_in[6];
    const float* Wlab   = (const float*)d_in[7];
    const float* temp   = (const float*)d_in[8];
    const float* startt = (const float*)d_in[9];
    const float* endt   = (const float*)d_in[10];
    const float* trans  = (const float*)d_in[11];
    float* out = (float*)d_out;

    ksplitA<<<(int)(((size_t)MM * DIN / 4) / 256), 256>>>(seq);
    ksplitB<<<dim3(DIN / 32, HH / 32), dim3(32, 8)>>>(Wtok);
    k0_labelh<<<dim3(HH / 128, NLB), 128>>>(ltab, Wlab);

    const int smem1 = 2 * STAGEB;   // 122880
    cudaFuncSetAttribute(k1_mma, cudaFuncAttributeMaxDynamicSharedMemorySize, smem1);
    k1_mma<<<dim3(HH / 256, MM / 128), 512, smem1>>>();

    const int smem2 = (NLB * HH + HH + 16) * (int)sizeof(float);
    cudaFuncSetAttribute(k2_ln_gelu_logits, cudaFuncAttributeMaxDynamicSharedMemorySize, smem2);
    k2_ln_gelu_logits<<<MM / RPB, 256, smem2>>>(gamma, beta, temp, out);

    k2b_rowmax<<<MM / 256, 256>>>(out);
    k3_crf<<<BB, 32>>>(out, labels, startt, endt, trans);
    k4_loss<<<1, 32>>>(out + (out_size - 1));
}